// round 16
// baseline (speedup 1.0000x reference)
#include <cuda_runtime.h>
#include <cuda_bf16.h>
#include <cuda_fp16.h>
#include <cstdint>

// ---------------- problem constants ----------------
#define BB   4
#define NQ   8192
#define DM   256
#define HH   8
#define LL   4
#define DHD  32
#define NVV  5440
#define PCOLS 288
#define K3   768          // query GEMM split-K: [A_hi | A_lo | A_hi] x [W_hi ; W_hi ; W_lo]
#define ASTR 512          // physical query-A storage: [A_hi | A_lo], 512 cols
#define NITER 24          // 768 / 32  (query GEMM)
#define NIT16 8           // 256 / 32  (fp16 GEMMs)
#define BK   32
#define VTILES 340        // value GEMM: 170 row-tiles x 2 col-tiles
#define L23_START 5120    // first row of level 2 (levels 2+3 = rows 5120..5439)
#define L23_ROWS  320

// conv_all block ranges (each block handles 1024 elements, 4 per thread)
#define CB_QA 8192                     // query splitA: 8192*1024 elems
#define CB_VA (CB_QA + 5440)           // value fp32->fp16: 5440*1024 elems
#define CB_WV (CB_VA + 64)             // W_v -> fp16 W^T (65536 elems)
#define CB_WO (CB_WV + 64)             // W_o -> fp16 W^T
#define CB_WQ (CB_WO + 96)             // Wcat split (+ bias)

__device__ __constant__ int   c_Wl[LL]   = {64, 32, 16, 8};
__device__ __constant__ int   c_lsi[LL]  = {0, 4096, 5120, 5376};
__device__ __constant__ float c_inv[LL]  = {1.f/64.f, 1.f/32.f, 1.f/16.f, 1.f/8.f};

// ---------------- static device scratch ----------------
__device__ __nv_bfloat16 g_Abig[32768 * ASTR];  // split-bf16 query A
__device__ __nv_bfloat16 g_WTQ[384 * K3];       // split W^T for Wcat
__device__ __half g_AVh[BB * NVV * DM];         // value, fp16
__device__ __half g_WTVh[DM * DM];              // W_v^T fp16
__device__ __half g_WTOh[DM * DM];              // W_o^T fp16
__device__ __half g_v[BB * NVV * DM];           // projected value, fp16
__device__ __half g_mid[32768 * DM];            // sampled output, fp16
__device__ float g_P[BB * NQ * PCOLS];
__device__ float g_bcat[PCOLS];

// ---------------- helpers ----------------
__device__ __forceinline__ uint32_t smem_u32(const void* p) {
    uint32_t a;
    asm("{ .reg .u64 t; cvta.to.shared.u64 t, %1; cvt.u32.u64 %0, t; }" : "=r"(a) : "l"(p));
    return a;
}
__device__ __forceinline__ void cpa16(uint32_t s, const void* g) {
    asm volatile("cp.async.cg.shared.global [%0], [%1], 16;" :: "r"(s), "l"(g));
}
#define CPA_COMMIT() asm volatile("cp.async.commit_group;" ::: "memory")
#define SWZ64(x) ((x) ^ (((x) >> 3) & 0x30))

__device__ __forceinline__ uint32_t pack_h2(float a, float b) {
    __half2 h = __floats2half2_rn(a, b);
    return *reinterpret_cast<uint32_t*>(&h);
}

__device__ __forceinline__ void ldsm4(uint32_t& r0, uint32_t& r1, uint32_t& r2, uint32_t& r3,
                                      uint32_t addr) {
    asm volatile("ldmatrix.sync.aligned.m8n8.x4.shared.b16 {%0,%1,%2,%3}, [%4];"
                 : "=r"(r0), "=r"(r1), "=r"(r2), "=r"(r3) : "r"(addr));
}
__device__ __forceinline__ void mma16816(float* c, uint32_t a0, uint32_t a1, uint32_t a2,
                                         uint32_t a3, uint32_t b0, uint32_t b1) {
    asm volatile("mma.sync.aligned.m16n8k16.row.col.f32.bf16.bf16.f32 "
                 "{%0,%1,%2,%3}, {%4,%5,%6,%7}, {%8,%9}, {%0,%1,%2,%3};"
                 : "+f"(c[0]), "+f"(c[1]), "+f"(c[2]), "+f"(c[3])
                 : "r"(a0), "r"(a1), "r"(a2), "r"(a3), "r"(b0), "r"(b1));
}
__device__ __forceinline__ void mma16816h(float* c, uint32_t a0, uint32_t a1, uint32_t a2,
                                          uint32_t a3, uint32_t b0, uint32_t b1) {
    asm volatile("mma.sync.aligned.m16n8k16.row.col.f32.f16.f16.f32 "
                 "{%0,%1,%2,%3}, {%4,%5,%6,%7}, {%8,%9}, {%0,%1,%2,%3};"
                 : "+f"(c[0]), "+f"(c[1]), "+f"(c[2]), "+f"(c[3])
                 : "r"(a0), "r"(a1), "r"(a2), "r"(a3), "r"(b0), "r"(b1));
}

// chunk j (0..23) -> element offset inside the 512-col query-A storage
__device__ __forceinline__ int a_chunk_off(int j) {
    int jj = (j < 16) ? j : (j - 16);
    return ((jj & 8) ? 256 : 0) + (jj & 7) * BK;
}

// ---------------- one-launch vectorized conversions ----------------
__device__ __forceinline__ uint32_t pack_bf2(float a, float b) {
    uint32_t r;
    asm("cvt.rn.bf16x2.f32 %0, %2, %1;" : "=r"(r) : "f"(a), "f"(b));   // lo=a, hi=b
    return r;
}
__device__ __forceinline__ void splitA4(const float* __restrict__ A,
                                        __nv_bfloat16* __restrict__ dst, int i4) {
    int base = i4 * 4;
    int r = base >> 8, c = base & 255;
    float4 v = *reinterpret_cast<const float4*>(A + base);
    float hx = __bfloat162float(__float2bfloat16(v.x));
    float hy = __bfloat162float(__float2bfloat16(v.y));
    float hz = __bfloat162float(__float2bfloat16(v.z));
    float hw = __bfloat162float(__float2bfloat16(v.w));
    uint2 hi = make_uint2(pack_bf2(hx, hy), pack_bf2(hz, hw));
    uint2 lo = make_uint2(pack_bf2(v.x - hx, v.y - hy), pack_bf2(v.z - hz, v.w - hw));
    __nv_bfloat16* p = dst + (size_t)r * ASTR + c;
    *reinterpret_cast<uint2*>(p)       = hi;
    *reinterpret_cast<uint2*>(p + 256) = lo;
}

__global__ void conv_all(const float* __restrict__ query, const float* __restrict__ value,
                         const float* __restrict__ Wv, const float* __restrict__ Wo,
                         const float* __restrict__ Wt, const float* __restrict__ bt,
                         const float* __restrict__ Wf, const float* __restrict__ bf,
                         const float* __restrict__ Wl, const float* __restrict__ bl,
                         const float* __restrict__ Wp, const float* __restrict__ bp) {
    int blk = blockIdx.x;
    int tid = threadIdx.x;
    if (blk < CB_QA) {
        splitA4(query, g_Abig, blk * 256 + tid);
    } else if (blk < CB_VA) {
        int base = ((blk - CB_QA) * 256 + tid) * 4;
        float4 v = *reinterpret_cast<const float4*>(value + base);
        uint2 o = make_uint2(pack_h2(v.x, v.y), pack_h2(v.z, v.w));
        *reinterpret_cast<uint2*>(g_AVh + base) = o;
    } else if (blk < CB_WO) {
        bool isV = blk < CB_WV;
        int i4 = ((blk - (isV ? CB_VA : CB_WV)) * 256 + tid);
        int base = i4 * 4;
        int n = base >> 8, k = base & 255;        // 4 consecutive k, same n
        const float* W = isV ? Wv : Wo;
        float v0 = W[(k + 0) * DM + n], v1 = W[(k + 1) * DM + n];
        float v2 = W[(k + 2) * DM + n], v3 = W[(k + 3) * DM + n];
        uint2 o = make_uint2(pack_h2(v0, v1), pack_h2(v2, v3));
        __half* dst = isV ? g_WTVh : g_WTOh;
        *reinterpret_cast<uint2*>(dst + (size_t)n * DM + k) = o;
    } else {
        int i4 = (blk - CB_WO) * 256 + tid;
        int base = i4 * 4;
        int n = base >> 8, k = base & 255;
        float v[4];
#pragma unroll
        for (int j = 0; j < 4; j++) {
            int kk = k + j;
            float x = 0.f;
            if      (n < 64)    x = Wt[kk * 64  + n];
            else if (n < 128)   x = Wf[kk * 64  + (n - 64)];
            else if (n < 160)   x = Wl[kk * 32  + (n - 128)];
            else if (n < PCOLS) x = Wp[kk * 128 + (n - 160)];
            v[j] = x;
        }
        float h0 = __bfloat162float(__float2bfloat16(v[0]));
        float h1 = __bfloat162float(__float2bfloat16(v[1]));
        float h2 = __bfloat162float(__float2bfloat16(v[2]));
        float h3 = __bfloat162float(__float2bfloat16(v[3]));
        uint2 hi = make_uint2(pack_bf2(h0, h1), pack_bf2(h2, h3));
        uint2 lo = make_uint2(pack_bf2(v[0] - h0, v[1] - h1), pack_bf2(v[2] - h2, v[3] - h3));
        __nv_bfloat16* p = g_WTQ + (size_t)n * K3 + k;
        *reinterpret_cast<uint2*>(p)       = hi;
        *reinterpret_cast<uint2*>(p + 256) = hi;
        *reinterpret_cast<uint2*>(p + 512) = lo;
        if (base < PCOLS) {
#pragma unroll
            for (int j = 0; j < 4; j++) {
                int i = base + j;
                if (i < PCOLS) {
                    float bv;
                    if      (i < 64)  bv = bt[i];
                    else if (i < 128) bv = bf[i - 64];
                    else if (i < 160) bv = bl[i - 128];
                    else              bv = bp[i - 160];
                    g_bcat[i] = bv;
                }
            }
        }
    }
}

// ---------------- query GEMM body: split-bf16, K3=768, 4-stage cp.async ----------------
__device__ __forceinline__ void gemm_bodyQ(const __nv_bfloat16* __restrict__ A,
                                           const __nv_bfloat16* __restrict__ Bt,
                                           const float* __restrict__ bias,
                                           float* __restrict__ C,
                                           int N, int rowBase, int colBase, uint32_t sb) {
    const int tid = threadIdx.x, wid = tid >> 5, lane = tid & 31;
    const int wm = wid >> 1, wn = wid & 1;

    auto load = [&](int j, int s) {
        uint32_t abase = sb + s * 16384;
        uint32_t bbase = abase + 8192;
        const __nv_bfloat16* ga = A  + (size_t)rowBase * ASTR + a_chunk_off(j);
        const __nv_bfloat16* gb = Bt + (size_t)colBase * K3 + j * BK;
#pragma unroll
        for (int it = 0; it < 2; it++) {
            int id = tid + it * 256;                // 0..511
            int r = id >> 2, c4 = (id & 3) * 16;
            uint32_t sw = SWZ64(r * 64 + c4);
            cpa16(abase + sw, (const char*)(ga + (size_t)r * ASTR) + c4);
            cpa16(bbase + sw, (const char*)(gb + (size_t)r * K3) + c4);
        }
        CPA_COMMIT();
    };

    float acc[2][8][4];
#pragma unroll
    for (int mi = 0; mi < 2; mi++)
#pragma unroll
        for (int ni = 0; ni < 8; ni++)
#pragma unroll
            for (int q = 0; q < 4; q++) acc[mi][ni][q] = 0.f;

    load(0, 0); load(1, 1); load(2, 2);

    const int aRow = (lane & 15);
    const int aK   = (lane >> 4) << 3;
    const int bRow = (lane & 7) + ((lane >> 4) << 3);
    const int bK   = ((lane >> 3) & 1) << 3;

    for (int i = 0; i < NITER; i++) {
        asm volatile("cp.async.wait_group 2;" ::: "memory");
        __syncthreads();
        if (i + 3 < NITER) load(i + 3, (i + 3) & 3);
        else CPA_COMMIT();

        uint32_t abase = sb + (i & 3) * 16384;
        uint32_t bbase = abase + 8192;
#pragma unroll
        for (int kk = 0; kk < BK; kk += 16) {
            uint32_t a[2][4];
#pragma unroll
            for (int mi = 0; mi < 2; mi++) {
                int row = wm * 32 + mi * 16 + aRow;
                ldsm4(a[mi][0], a[mi][1], a[mi][2], a[mi][3],
                      abase + SWZ64(row * 64 + (kk + aK) * 2));
            }
            uint32_t b[4][4];
#pragma unroll
            for (int ng = 0; ng < 4; ng++) {
                int row = wn * 64 + ng * 16 + bRow;
                ldsm4(b[ng][0], b[ng][1], b[ng][2], b[ng][3],
                      bbase + SWZ64(row * 64 + (kk + bK) * 2));
            }
#pragma unroll
            for (int mi = 0; mi < 2; mi++)
#pragma unroll
                for (int ni = 0; ni < 8; ni++) {
                    int ng = ni >> 1, half = ni & 1;
                    mma16816(acc[mi][ni], a[mi][0], a[mi][1], a[mi][2], a[mi][3],
                             b[ng][half * 2], b[ng][half * 2 + 1]);
                }
        }
    }

    const int g = lane >> 2, tig = lane & 3;
#pragma unroll
    for (int mi = 0; mi < 2; mi++) {
        int r0 = rowBase + wm * 32 + mi * 16 + g;
        int r1 = r0 + 8;
#pragma unroll
        for (int ni = 0; ni < 8; ni++) {
            int c = colBase + wn * 64 + ni * 8 + tig * 2;
            if (c < N) {
                float bx = __ldg(&bias[c]), by = __ldg(&bias[c + 1]);
                float2 v0 = make_float2(acc[mi][ni][0] + bx, acc[mi][ni][1] + by);
                float2 v1 = make_float2(acc[mi][ni][2] + bx, acc[mi][ni][3] + by);
                *reinterpret_cast<float2*>(C + (size_t)r0 * N + c) = v0;
                *reinterpret_cast<float2*>(C + (size_t)r1 * N + c) = v1;
            }
        }
    }
}

// ---------------- fp16 GEMM body: K=256 single stream, 4-stage cp.async ----------------
template <bool HALF_OUT>
__device__ __forceinline__ void gemm_body16(const __half* __restrict__ A,
                                            const __half* __restrict__ Bt,
                                            const float* __restrict__ bias,
                                            void* __restrict__ Cv,
                                            int rowBase, int colBase, uint32_t sb) {
    const int tid = threadIdx.x, wid = tid >> 5, lane = tid & 31;
    const int wm = wid >> 1, wn = wid & 1;

    auto load = [&](int j, int s) {
        uint32_t abase = sb + s * 16384;
        uint32_t bbase = abase + 8192;
        const __half* ga = A  + (size_t)rowBase * DM + j * BK;
        const __half* gb = Bt + (size_t)colBase * DM + j * BK;
#pragma unroll
        for (int it = 0; it < 2; it++) {
            int id = tid + it * 256;
            int r = id >> 2, c4 = (id & 3) * 16;
            uint32_t sw = SWZ64(r * 64 + c4);
            cpa16(abase + sw, (const char*)(ga + (size_t)r * DM) + c4);
            cpa16(bbase + sw, (const char*)(gb + (size_t)r * DM) + c4);
        }
        CPA_COMMIT();
    };

    float acc[2][8][4];
#pragma unroll
    for (int mi = 0; mi < 2; mi++)
#pragma unroll
        for (int ni = 0; ni < 8; ni++)
#pragma unroll
            for (int q = 0; q < 4; q++) acc[mi][ni][q] = 0.f;

    load(0, 0); load(1, 1); load(2, 2);

    const int aRow = (lane & 15);
    const int aK   = (lane >> 4) << 3;
    const int bRow = (lane & 7) + ((lane >> 4) << 3);
    const int bK   = ((lane >> 3) & 1) << 3;

    for (int i = 0; i < NIT16; i++) {
        asm volatile("cp.async.wait_group 2;" ::: "memory");
        __syncthreads();
        if (i + 3 < NIT16) load(i + 3, (i + 3) & 3);
        else CPA_COMMIT();

        uint32_t abase = sb + (i & 3) * 16384;
        uint32_t bbase = abase + 8192;
#pragma unroll
        for (int kk = 0; kk < BK; kk += 16) {
            uint32_t a[2][4];
#pragma unroll
            for (int mi = 0; mi < 2; mi++) {
                int row = wm * 32 + mi * 16 + aRow;
                ldsm4(a[mi][0], a[mi][1], a[mi][2], a[mi][3],
                      abase + SWZ64(row * 64 + (kk + aK) * 2));
            }
            uint32_t b[4][4];
#pragma unroll
            for (int ng = 0; ng < 4; ng++) {
                int row = wn * 64 + ng * 16 + bRow;
                ldsm4(b[ng][0], b[ng][1], b[ng][2], b[ng][3],
                      bbase + SWZ64(row * 64 + (kk + bK) * 2));
            }
#pragma unroll
            for (int mi = 0; mi < 2; mi++)
#pragma unroll
                for (int ni = 0; ni < 8; ni++) {
                    int ng = ni >> 1, half = ni & 1;
                    mma16816h(acc[mi][ni], a[mi][0], a[mi][1], a[mi][2], a[mi][3],
                              b[ng][half * 2], b[ng][half * 2 + 1]);
                }
        }
    }

    const int g = lane >> 2, tig = lane & 3;
#pragma unroll
    for (int mi = 0; mi < 2; mi++) {
        int r0 = rowBase + wm * 32 + mi * 16 + g;
        int r1 = r0 + 8;
#pragma unroll
        for (int ni = 0; ni < 8; ni++) {
            int c = colBase + wn * 64 + ni * 8 + tig * 2;
            float bx = __ldg(&bias[c]), by = __ldg(&bias[c + 1]);
            if (HALF_OUT) {
                __half* C = (__half*)Cv;
                *reinterpret_cast<uint32_t*>(C + (size_t)r0 * DM + c) =
                    pack_h2(acc[mi][ni][0] + bx, acc[mi][ni][1] + by);
                *reinterpret_cast<uint32_t*>(C + (size_t)r1 * DM + c) =
                    pack_h2(acc[mi][ni][2] + bx, acc[mi][ni][3] + by);
            } else {
                float* C = (float*)Cv;
                float2 v0 = make_float2(acc[mi][ni][0] + bx, acc[mi][ni][1] + by);
                float2 v1 = make_float2(acc[mi][ni][2] + bx, acc[mi][ni][3] + by);
                *reinterpret_cast<float2*>(C + (size_t)r0 * DM + c) = v0;
                *reinterpret_cast<float2*>(C + (size_t)r1 * DM + c) = v1;
            }
        }
    }
}

// fused value (fp16) + query (split-bf16) GEMM
__global__ __launch_bounds__(256, 2)
void gemm_vq(const float* __restrict__ biasV, float* __restrict__ CQ) {
    extern __shared__ char smem[];                  // 4 * 16384
    uint32_t sb = smem_u32(smem);
    int t = blockIdx.x;
    if (t < VTILES) {
        int rowBase = (t >> 1) * 128, colBase = (t & 1) * 128;
        gemm_body16<true>(g_AVh, g_WTVh, biasV, g_v, rowBase, colBase, sb);
    } else {
        t -= VTILES;
        int rowBase = (t / 3) * 128, colBase = (t % 3) * 128;
        gemm_bodyQ(g_Abig, g_WTQ, g_bcat, CQ, PCOLS, rowBase, colBase, sb);
    }
}

// output GEMM (fp16 inputs, fp32 out)
__global__ __launch_bounds__(256, 2)
void gemm_out(const float* __restrict__ bias, float* __restrict__ C) {
    extern __shared__ char smem[];
    uint32_t sb = smem_u32(smem);
    int rowBase = (blockIdx.x >> 1) * 128, colBase = (blockIdx.x & 1) * 128;
    gemm_body16<false>(g_mid, g_WTOh, bias, C, rowBase, colBase, sb);
}

// ---------------- deformable sampling: 4 gids/warp + smem-staged levels 2/3 ----------------
__device__ __forceinline__ float tanh_approx(float x) {
    float r;
    asm("tanh.approx.f32 %0, %1;" : "=f"(r) : "f"(x));
    return r;
}

// CTA covers 32 consecutive h-major gids -> CTA-uniform (b,h). Levels 2+3 of that
// (b,h) (rows 5120..5439, 20 KB fp16) are staged into SMEM once; taps t in [32,64)
// are served from SMEM (tap layout is level-ordered), t in [0,32) from L2.
__global__ __launch_bounds__(256)
void sample_kernel(const float* __restrict__ refp) {
    __shared__ float2 s_tap[8][4][64];         // 16 KB
    __shared__ __half s_v23[L23_ROWS * DHD];   // 20 KB: levels 2+3 slice

    const int warp = threadIdx.x >> 5;
    const int lane = threadIdx.x & 31;
    const int gbase = (blockIdx.x * 8 + warp) * 4;  // h-major: gid = h*32768 + bq

    // ---- stage levels 2+3 for this CTA's (b,h) ----
    {
        const int gid0 = blockIdx.x * 32;
        const int hC = gid0 >> 15;
        const int bC = (gid0 & 32767) >> 13;
        const uint2* __restrict__ src = reinterpret_cast<const uint2*>(
            g_v + (size_t)bC * NVV * DM + (size_t)L23_START * DM + hC * DHD);
        uint2* dst = reinterpret_cast<uint2*>(s_v23);
#pragma unroll
        for (int i = threadIdx.x; i < L23_ROWS * 8; i += 256) {
            int r = i >> 3, cc = i & 7;
            dst[i] = src[(size_t)r * (DM / 4) + cc];
        }
    }

    // ---- tap prep: two passes, 32 lanes each covering 2 gids ----
#pragma unroll
    for (int jj = 0; jj < 2; jj++) {
        const int sub = (lane >> 4) + jj * 2;       // 0..3
        const int li  = lane & 15;                  // sample 0..15
        const int gid = gbase + sub;
        const int h  = gid >> 15;
        const int bq = gid & 32767;

        const float* __restrict__ P = g_P + (size_t)bq * PCOLS;
        const int hL = h * LL;

        const int l  = li >> 2, k = li & 3;
        const int kt = k >> 1,  kf = k & 1;
        const float t = tanh_approx(P[(hL + l) * 2 + kt]);
        const float f = tanh_approx(P[64 + (hL + l) * 2 + kf]);

        float e0 = P[128 + hL + 0], e1 = P[128 + hL + 1];
        float e2 = P[128 + hL + 2], e3 = P[128 + hL + 3];
        float mx = fmaxf(fmaxf(e0, e1), fmaxf(e2, e3));
        float x0e = __expf(e0 - mx), x1e = __expf(e1 - mx);
        float x2e = __expf(e2 - mx), x3e = __expf(e3 - mx);
        float lsum = x0e + x1e + x2e + x3e;
        float lwv = (l == 0 ? x0e : l == 1 ? x1e : l == 2 ? x2e : x3e);

        const float* pp = P + 160 + (hL + l) * 4;
        float p0 = pp[0], p1 = pp[1], p2 = pp[2], p3 = pp[3];
        float pm = fmaxf(fmaxf(p0, p1), fmaxf(p2, p3));
        float q0 = __expf(p0 - pm), q1 = __expf(p1 - pm);
        float q2 = __expf(p2 - pm), q3 = __expf(p3 - pm);
        float psum = q0 + q1 + q2 + q3;
        float pwv = (k == 0 ? q0 : k == 1 ? q1 : k == 2 ? q2 : q3);

        const float a = __fdividef(lwv * pwv, lsum * psum);

        const float* rp = refp + (size_t)bq * (LL * 2);
        const int   Wl = c_Wl[l];
        const int   start = c_lsi[l];
        const float fWl = (float)Wl;
        float lx = rp[l * 2 + 0] + t * c_inv[l];
        float ly = rp[l * 2 + 1] + f * c_inv[l];
        lx = fminf(fmaxf(lx, 0.f), 1.f);
        ly = fminf(fmaxf(ly, 0.f), 1.f);
        float x = lx * fWl - 0.5f;
        float y = ly * fWl - 0.5f;       // Hl == Wl for all levels
        float x0f = floorf(x), y0f = floorf(y);
        float wx1 = x - x0f, wy1 = y - y0f;
        float wx0 = 1.f - wx1, wy0 = 1.f - wy1;
        int x0 = (int)x0f, y0 = (int)y0f;

#pragma unroll
        for (int j = 0; j < 4; j++) {
            int xi = x0 + (j & 1), yi = y0 + (j >> 1);
            float w = a * ((j & 1) ? wx1 : wx0) * ((j >> 1) ? wy1 : wy0);
            bool valid = (xi >= 0) & (xi < Wl) & (yi >= 0) & (yi < Wl);
            int xc = min(max(xi, 0), Wl - 1);
            int yc = min(max(yi, 0), Wl - 1);
            s_tap[warp][sub][li * 4 + j] =
                make_float2(valid ? w : 0.f, __int_as_float(start + yc * Wl + xc));
        }
    }
    __syncthreads();   // staging + taps complete

    // ---- gather: 8 lanes per gid, 4 channels per lane ----
    const int sub = lane >> 3;                      // 0..3
    const int ch  = (lane & 7) * 4;                 // channel base 0..28
    const int gid = gbase + sub;
    const int h  = gid >> 15;
    const int bq = gid & 32767;
    const int b  = bq >> 13;                        // NQ=8192

    const uint2* __restrict__ vb = reinterpret_cast<const uint2*>(
        g_v + (size_t)b * NVV * DM + h * DHD + ch);
    float acc0 = 0.f, acc1 = 0.f, acc2 = 0.f, acc3 = 0.f;

    // levels 0,1: L2 gather
#pragma unroll 16
    for (int t = 0; t < 32; t++) {
        float2 tp = s_tap[warp][sub][t];
        uint2 raw = vb[(size_t)__float_as_int(tp.y) * (DM / 4)];
        float2 v01 = __half22float2(*reinterpret_cast<__half2*>(&raw.x));
        float2 v23 = __half22float2(*reinterpret_cast<__half2*>(&raw.y));
        acc0 += tp.x * v01.x;
        acc1 += tp.x * v01.y;
        acc2 += tp.x * v23.x;
        acc3 += tp.x * v23.y;
    }
    // levels 2,3: SMEM gather
#pragma unroll 16
    for (int t = 32; t < 64; t++) {
        float2 tp = s_tap[warp][sub][t];
        int r = __float_as_int(tp.y) - L23_START;
        uint2 raw = *reinterpret_cast<const uint2*>(s_v23 + r * DHD + ch);
        float2 v01 = __half22float2(*reinterpret_cast<__half2*>(&raw.x));
        float2 v23 = __half22float2(*reinterpret_cast<__half2*>(&raw.y));
        acc0 += tp.x * v01.x;
        acc1 += tp.x * v01.y;
        acc2 += tp.x * v23.x;
        acc3 += tp.x * v23.y;
    }

    // write fp16 quad into g_mid for the output GEMM
    const int col = h * DHD + ch;
    *reinterpret_cast<uint2*>(g_mid + (size_t)bq * DM + col) =
        make_uint2(pack_h2(acc0, acc1), pack_h2(acc2, acc3));
}

// ---------------- launch ----------------
extern "C" void kernel_launch(void* const* d_in, const int* in_sizes, int n_in,
                              void* d_out, int out_size) {
    const float* query  = (const float*)d_in[0];
    const float* refp   = (const float*)d_in[1];
    const float* value  = (const float*)d_in[2];
    const float* W_time = (const float*)d_in[5];
    const float* b_time = (const float*)d_in[6];
    const float* W_freq = (const float*)d_in[7];
    const float* b_freq = (const float*)d_in[8];
    const float* W_lvl  = (const float*)d_in[9];
    const float* b_lvl  = (const float*)d_in[10];
    const float* W_pt   = (const float*)d_in[11];
    const float* b_pt   = (const float*)d_in[12];
    const float* W_v    = (const float*)d_in[13];
    const float* b_v    = (const float*)d_in[14];
    const float* W_o    = (const float*)d_in[15];
    const float* b_o    = (const float*)d_in[16];
    float* out = (float*)d_out;

    float* p_P;
    cudaGetSymbolAddress((void**)&p_P, g_P);

    const int GEMM_SMEM = 4 * 16384;   // 64 KB
    cudaFuncSetAttribute(gemm_vq,  cudaFuncAttributeMaxDynamicSharedMemorySize, GEMM_SMEM);
    cudaFuncSetAttribute(gemm_out, cudaFuncAttributeMaxDynamicSharedMemorySize, GEMM_SMEM);

    // 1) all conversions in ONE vectorized launch
    conv_all<<<CB_WQ, 256>>>(query, value, W_v, W_o,
                             W_time, b_time, W_freq, b_freq,
                             W_lvl, b_lvl, W_pt, b_pt);

    // 2) fused value(fp16) + query(split-bf16) GEMMs; value out = fp16 g_v
    gemm_vq<<<VTILES + 768, 256, GEMM_SMEM>>>(b_v, p_P);

    // 3) deformable sampling (smem-staged levels 2/3) -> fp16 g_mid
    sample_kernel<<<(BB * NQ * HH) / 32, 256>>>(refp);

    // 4) output GEMM (fp16): out = mid @ W_o + b_o   [32768 x 256]
    gemm_out<<<512, 256, GEMM_SMEM>>>(b_o, out);
}

// round 17
// speedup vs baseline: 1.1888x; 1.1888x over previous
#include <cuda_runtime.h>
#include <cuda_bf16.h>
#include <cuda_fp16.h>
#include <cstdint>

// ---------------- problem constants ----------------
#define BB   4
#define NQ   8192
#define DM   256
#define HH   8
#define LL   4
#define DHD  32
#define NVV  5440
#define PCOLS 288
#define K3   768          // query GEMM split-K: [A_hi | A_lo | A_hi] x [W_hi ; W_hi ; W_lo]
#define ASTR 512          // physical query-A storage: [A_hi | A_lo], 512 cols
#define NITER 24          // 768 / 32  (query GEMM)
#define NIT16 8           // 256 / 32  (fp16 GEMMs)
#define BK   32
#define VTILES 340        // value GEMM: 170 row-tiles x 2 col-tiles
#define QFULL  512        // query full tiles: 256 row-tiles x 2 col-tiles
#define QNARROW 256       // query narrow tiles: 256 row-tiles x 1 (cols 256..287)

// conv_all block ranges (each block handles 1024 elements, 4 per thread)
#define CB_QA 8192                     // query splitA: 8192*1024 elems
#define CB_VA (CB_QA + 5440)           // value fp32->fp16: 5440*1024 elems
#define CB_WV (CB_VA + 64)             // W_v -> fp16 W^T (65536 elems)
#define CB_WO (CB_WV + 64)             // W_o -> fp16 W^T
#define CB_WQ (CB_WO + 96)             // Wcat split (+ bias)

__device__ __constant__ int   c_Wl[LL]   = {64, 32, 16, 8};
__device__ __constant__ int   c_lsi[LL]  = {0, 4096, 5120, 5376};
__device__ __constant__ float c_inv[LL]  = {1.f/64.f, 1.f/32.f, 1.f/16.f, 1.f/8.f};

// ---------------- static device scratch ----------------
__device__ __nv_bfloat16 g_Abig[32768 * ASTR];  // split-bf16 query A
__device__ __nv_bfloat16 g_WTQ[384 * K3];       // split W^T for Wcat
__device__ __half g_AVh[BB * NVV * DM];         // value, fp16
__device__ __half g_WTVh[DM * DM];              // W_v^T fp16
__device__ __half g_WTOh[DM * DM];              // W_o^T fp16
__device__ __half g_v[BB * NVV * DM];           // projected value, fp16
__device__ __half g_mid[32768 * DM];            // sampled output, fp16
__device__ float g_P[BB * NQ * PCOLS];
__device__ float g_bcat[PCOLS];

// ---------------- helpers ----------------
__device__ __forceinline__ uint32_t smem_u32(const void* p) {
    uint32_t a;
    asm("{ .reg .u64 t; cvta.to.shared.u64 t, %1; cvt.u32.u64 %0, t; }" : "=r"(a) : "l"(p));
    return a;
}
__device__ __forceinline__ void cpa16(uint32_t s, const void* g) {
    asm volatile("cp.async.cg.shared.global [%0], [%1], 16;" :: "r"(s), "l"(g));
}
#define CPA_COMMIT() asm volatile("cp.async.commit_group;" ::: "memory")
#define SWZ64(x) ((x) ^ (((x) >> 3) & 0x30))

__device__ __forceinline__ uint32_t pack_h2(float a, float b) {
    __half2 h = __floats2half2_rn(a, b);
    return *reinterpret_cast<uint32_t*>(&h);
}

__device__ __forceinline__ void ldsm4(uint32_t& r0, uint32_t& r1, uint32_t& r2, uint32_t& r3,
                                      uint32_t addr) {
    asm volatile("ldmatrix.sync.aligned.m8n8.x4.shared.b16 {%0,%1,%2,%3}, [%4];"
                 : "=r"(r0), "=r"(r1), "=r"(r2), "=r"(r3) : "r"(addr));
}
__device__ __forceinline__ void mma16816(float* c, uint32_t a0, uint32_t a1, uint32_t a2,
                                         uint32_t a3, uint32_t b0, uint32_t b1) {
    asm volatile("mma.sync.aligned.m16n8k16.row.col.f32.bf16.bf16.f32 "
                 "{%0,%1,%2,%3}, {%4,%5,%6,%7}, {%8,%9}, {%0,%1,%2,%3};"
                 : "+f"(c[0]), "+f"(c[1]), "+f"(c[2]), "+f"(c[3])
                 : "r"(a0), "r"(a1), "r"(a2), "r"(a3), "r"(b0), "r"(b1));
}
__device__ __forceinline__ void mma16816h(float* c, uint32_t a0, uint32_t a1, uint32_t a2,
                                          uint32_t a3, uint32_t b0, uint32_t b1) {
    asm volatile("mma.sync.aligned.m16n8k16.row.col.f32.f16.f16.f32 "
                 "{%0,%1,%2,%3}, {%4,%5,%6,%7}, {%8,%9}, {%0,%1,%2,%3};"
                 : "+f"(c[0]), "+f"(c[1]), "+f"(c[2]), "+f"(c[3])
                 : "r"(a0), "r"(a1), "r"(a2), "r"(a3), "r"(b0), "r"(b1));
}

// chunk j (0..23) -> element offset inside the 512-col query-A storage
__device__ __forceinline__ int a_chunk_off(int j) {
    int jj = (j < 16) ? j : (j - 16);
    return ((jj & 8) ? 256 : 0) + (jj & 7) * BK;
}

// ---------------- one-launch vectorized conversions ----------------
__device__ __forceinline__ uint32_t pack_bf2(float a, float b) {
    uint32_t r;
    asm("cvt.rn.bf16x2.f32 %0, %2, %1;" : "=r"(r) : "f"(a), "f"(b));   // lo=a, hi=b
    return r;
}
__device__ __forceinline__ void splitA4(const float* __restrict__ A,
                                        __nv_bfloat16* __restrict__ dst, int i4) {
    int base = i4 * 4;
    int r = base >> 8, c = base & 255;
    float4 v = *reinterpret_cast<const float4*>(A + base);
    float hx = __bfloat162float(__float2bfloat16(v.x));
    float hy = __bfloat162float(__float2bfloat16(v.y));
    float hz = __bfloat162float(__float2bfloat16(v.z));
    float hw = __bfloat162float(__float2bfloat16(v.w));
    uint2 hi = make_uint2(pack_bf2(hx, hy), pack_bf2(hz, hw));
    uint2 lo = make_uint2(pack_bf2(v.x - hx, v.y - hy), pack_bf2(v.z - hz, v.w - hw));
    __nv_bfloat16* p = dst + (size_t)r * ASTR + c;
    *reinterpret_cast<uint2*>(p)       = hi;
    *reinterpret_cast<uint2*>(p + 256) = lo;
}

__global__ void conv_all(const float* __restrict__ query, const float* __restrict__ value,
                         const float* __restrict__ Wv, const float* __restrict__ Wo,
                         const float* __restrict__ Wt, const float* __restrict__ bt,
                         const float* __restrict__ Wf, const float* __restrict__ bf,
                         const float* __restrict__ Wl, const float* __restrict__ bl,
                         const float* __restrict__ Wp, const float* __restrict__ bp) {
    int blk = blockIdx.x;
    int tid = threadIdx.x;
    if (blk < CB_QA) {
        splitA4(query, g_Abig, blk * 256 + tid);
    } else if (blk < CB_VA) {
        int base = ((blk - CB_QA) * 256 + tid) * 4;
        float4 v = *reinterpret_cast<const float4*>(value + base);
        uint2 o = make_uint2(pack_h2(v.x, v.y), pack_h2(v.z, v.w));
        *reinterpret_cast<uint2*>(g_AVh + base) = o;
    } else if (blk < CB_WO) {
        bool isV = blk < CB_WV;
        int i4 = ((blk - (isV ? CB_VA : CB_WV)) * 256 + tid);
        int base = i4 * 4;
        int n = base >> 8, k = base & 255;        // 4 consecutive k, same n
        const float* W = isV ? Wv : Wo;
        float v0 = W[(k + 0) * DM + n], v1 = W[(k + 1) * DM + n];
        float v2 = W[(k + 2) * DM + n], v3 = W[(k + 3) * DM + n];
        uint2 o = make_uint2(pack_h2(v0, v1), pack_h2(v2, v3));
        __half* dst = isV ? g_WTVh : g_WTOh;
        *reinterpret_cast<uint2*>(dst + (size_t)n * DM + k) = o;
    } else {
        int i4 = (blk - CB_WO) * 256 + tid;
        int base = i4 * 4;
        int n = base >> 8, k = base & 255;
        float v[4];
#pragma unroll
        for (int j = 0; j < 4; j++) {
            int kk = k + j;
            float x = 0.f;
            if      (n < 64)    x = Wt[kk * 64  + n];
            else if (n < 128)   x = Wf[kk * 64  + (n - 64)];
            else if (n < 160)   x = Wl[kk * 32  + (n - 128)];
            else if (n < PCOLS) x = Wp[kk * 128 + (n - 160)];
            v[j] = x;
        }
        float h0 = __bfloat162float(__float2bfloat16(v[0]));
        float h1 = __bfloat162float(__float2bfloat16(v[1]));
        float h2 = __bfloat162float(__float2bfloat16(v[2]));
        float h3 = __bfloat162float(__float2bfloat16(v[3]));
        uint2 hi = make_uint2(pack_bf2(h0, h1), pack_bf2(h2, h3));
        uint2 lo = make_uint2(pack_bf2(v[0] - h0, v[1] - h1), pack_bf2(v[2] - h2, v[3] - h3));
        __nv_bfloat16* p = g_WTQ + (size_t)n * K3 + k;
        *reinterpret_cast<uint2*>(p)       = hi;
        *reinterpret_cast<uint2*>(p + 256) = hi;
        *reinterpret_cast<uint2*>(p + 512) = lo;
        if (base < PCOLS) {
#pragma unroll
            for (int j = 0; j < 4; j++) {
                int i = base + j;
                if (i < PCOLS) {
                    float bv;
                    if      (i < 64)  bv = bt[i];
                    else if (i < 128) bv = bf[i - 64];
                    else if (i < 160) bv = bl[i - 128];
                    else              bv = bp[i - 160];
                    g_bcat[i] = bv;
                }
            }
        }
    }
}

// ---------------- query GEMM body: split-bf16, K3=768, 4-stage cp.async ----------------
__device__ __forceinline__ void gemm_bodyQ(const __nv_bfloat16* __restrict__ A,
                                           const __nv_bfloat16* __restrict__ Bt,
                                           const float* __restrict__ bias,
                                           float* __restrict__ C,
                                           int N, int rowBase, int colBase, uint32_t sb) {
    const int tid = threadIdx.x, wid = tid >> 5, lane = tid & 31;
    const int wm = wid >> 1, wn = wid & 1;

    auto load = [&](int j, int s) {
        uint32_t abase = sb + s * 16384;
        uint32_t bbase = abase + 8192;
        const __nv_bfloat16* ga = A  + (size_t)rowBase * ASTR + a_chunk_off(j);
        const __nv_bfloat16* gb = Bt + (size_t)colBase * K3 + j * BK;
#pragma unroll
        for (int it = 0; it < 2; it++) {
            int id = tid + it * 256;                // 0..511
            int r = id >> 2, c4 = (id & 3) * 16;
            uint32_t sw = SWZ64(r * 64 + c4);
            cpa16(abase + sw, (const char*)(ga + (size_t)r * ASTR) + c4);
            cpa16(bbase + sw, (const char*)(gb + (size_t)r * K3) + c4);
        }
        CPA_COMMIT();
    };

    float acc[2][8][4];
#pragma unroll
    for (int mi = 0; mi < 2; mi++)
#pragma unroll
        for (int ni = 0; ni < 8; ni++)
#pragma unroll
            for (int q = 0; q < 4; q++) acc[mi][ni][q] = 0.f;

    load(0, 0); load(1, 1); load(2, 2);

    const int aRow = (lane & 15);
    const int aK   = (lane >> 4) << 3;
    const int bRow = (lane & 7) + ((lane >> 4) << 3);
    const int bK   = ((lane >> 3) & 1) << 3;

    for (int i = 0; i < NITER; i++) {
        asm volatile("cp.async.wait_group 2;" ::: "memory");
        __syncthreads();
        if (i + 3 < NITER) load(i + 3, (i + 3) & 3);
        else CPA_COMMIT();

        uint32_t abase = sb + (i & 3) * 16384;
        uint32_t bbase = abase + 8192;
#pragma unroll
        for (int kk = 0; kk < BK; kk += 16) {
            uint32_t a[2][4];
#pragma unroll
            for (int mi = 0; mi < 2; mi++) {
                int row = wm * 32 + mi * 16 + aRow;
                ldsm4(a[mi][0], a[mi][1], a[mi][2], a[mi][3],
                      abase + SWZ64(row * 64 + (kk + aK) * 2));
            }
            uint32_t b[4][4];
#pragma unroll
            for (int ng = 0; ng < 4; ng++) {
                int row = wn * 64 + ng * 16 + bRow;
                ldsm4(b[ng][0], b[ng][1], b[ng][2], b[ng][3],
                      bbase + SWZ64(row * 64 + (kk + bK) * 2));
            }
#pragma unroll
            for (int mi = 0; mi < 2; mi++)
#pragma unroll
                for (int ni = 0; ni < 8; ni++) {
                    int ng = ni >> 1, half = ni & 1;
                    mma16816(acc[mi][ni], a[mi][0], a[mi][1], a[mi][2], a[mi][3],
                             b[ng][half * 2], b[ng][half * 2 + 1]);
                }
        }
    }

    const int g = lane >> 2, tig = lane & 3;
#pragma unroll
    for (int mi = 0; mi < 2; mi++) {
        int r0 = rowBase + wm * 32 + mi * 16 + g;
        int r1 = r0 + 8;
#pragma unroll
        for (int ni = 0; ni < 8; ni++) {
            int c = colBase + wn * 64 + ni * 8 + tig * 2;
            if (c < N) {
                float bx = __ldg(&bias[c]), by = __ldg(&bias[c + 1]);
                float2 v0 = make_float2(acc[mi][ni][0] + bx, acc[mi][ni][1] + by);
                float2 v1 = make_float2(acc[mi][ni][2] + bx, acc[mi][ni][3] + by);
                *reinterpret_cast<float2*>(C + (size_t)r0 * N + c) = v0;
                *reinterpret_cast<float2*>(C + (size_t)r1 * N + c) = v1;
            }
        }
    }
}

// ---------------- narrow query GEMM body: 128x32 tile (cols 256..287) ----------------
// 8 warps, warp tile 16x32, 4 MMAs per k16 step.
__device__ __forceinline__ void gemm_bodyQN(const __nv_bfloat16* __restrict__ A,
                                            const __nv_bfloat16* __restrict__ Bt,
                                            const float* __restrict__ bias,
                                            float* __restrict__ C,
                                            int rowBase, uint32_t sb) {
    const int tid = threadIdx.x, wid = tid >> 5, lane = tid & 31;
    const int colBase = 256;

    auto load = [&](int j, int s) {
        uint32_t abase = sb + s * 16384;
        uint32_t bbase = abase + 8192;
        const __nv_bfloat16* ga = A  + (size_t)rowBase * ASTR + a_chunk_off(j);
        const __nv_bfloat16* gb = Bt + (size_t)colBase * K3 + j * BK;
#pragma unroll
        for (int it = 0; it < 2; it++) {            // A: 512 chunks
            int id = tid + it * 256;
            int r = id >> 2, c4 = (id & 3) * 16;
            uint32_t sw = SWZ64(r * 64 + c4);
            cpa16(abase + sw, (const char*)(ga + (size_t)r * ASTR) + c4);
        }
        if (tid < 128) {                            // B: 32 rows x 64 B = 128 chunks
            int r = tid >> 2, c4 = (tid & 3) * 16;
            uint32_t sw = SWZ64(r * 64 + c4);
            cpa16(bbase + sw, (const char*)(gb + (size_t)r * K3) + c4);
        }
        CPA_COMMIT();
    };

    float acc[4][4];
#pragma unroll
    for (int ni = 0; ni < 4; ni++)
#pragma unroll
        for (int q = 0; q < 4; q++) acc[ni][q] = 0.f;

    load(0, 0); load(1, 1); load(2, 2);

    const int aRow = (lane & 15);
    const int aK   = (lane >> 4) << 3;
    const int bRow = (lane & 7) + ((lane >> 4) << 3);
    const int bK   = ((lane >> 3) & 1) << 3;

    for (int i = 0; i < NITER; i++) {
        asm volatile("cp.async.wait_group 2;" ::: "memory");
        __syncthreads();
        if (i + 3 < NITER) load(i + 3, (i + 3) & 3);
        else CPA_COMMIT();

        uint32_t abase = sb + (i & 3) * 16384;
        uint32_t bbase = abase + 8192;
#pragma unroll
        for (int kk = 0; kk < BK; kk += 16) {
            uint32_t a[4];
            {
                int row = wid * 16 + aRow;
                ldsm4(a[0], a[1], a[2], a[3], abase + SWZ64(row * 64 + (kk + aK) * 2));
            }
            uint32_t b[2][4];
#pragma unroll
            for (int ng = 0; ng < 2; ng++) {
                int row = ng * 16 + bRow;
                ldsm4(b[ng][0], b[ng][1], b[ng][2], b[ng][3],
                      bbase + SWZ64(row * 64 + (kk + bK) * 2));
            }
#pragma unroll
            for (int ni = 0; ni < 4; ni++) {
                int ng = ni >> 1, half = ni & 1;
                mma16816(acc[ni], a[0], a[1], a[2], a[3],
                         b[ng][half * 2], b[ng][half * 2 + 1]);
            }
        }
    }

    const int g = lane >> 2, tig = lane & 3;
    int r0 = rowBase + wid * 16 + g;
    int r1 = r0 + 8;
#pragma unroll
    for (int ni = 0; ni < 4; ni++) {
        int c = colBase + ni * 8 + tig * 2;         // 256..287, all < PCOLS
        float bx = __ldg(&bias[c]), by = __ldg(&bias[c + 1]);
        float2 v0 = make_float2(acc[ni][0] + bx, acc[ni][1] + by);
        float2 v1 = make_float2(acc[ni][2] + bx, acc[ni][3] + by);
        *reinterpret_cast<float2*>(C + (size_t)r0 * PCOLS + c) = v0;
        *reinterpret_cast<float2*>(C + (size_t)r1 * PCOLS + c) = v1;
    }
}

// ---------------- fp16 GEMM body: K=256 single stream, 4-stage cp.async ----------------
template <bool HALF_OUT>
__device__ __forceinline__ void gemm_body16(const __half* __restrict__ A,
                                            const __half* __restrict__ Bt,
                                            const float* __restrict__ bias,
                                            void* __restrict__ Cv,
                                            int rowBase, int colBase, uint32_t sb) {
    const int tid = threadIdx.x, wid = tid >> 5, lane = tid & 31;
    const int wm = wid >> 1, wn = wid & 1;

    auto load = [&](int j, int s) {
        uint32_t abase = sb + s * 16384;
        uint32_t bbase = abase + 8192;
        const __half* ga = A  + (size_t)rowBase * DM + j * BK;
        const __half* gb = Bt + (size_t)colBase * DM + j * BK;
#pragma unroll
        for (int it = 0; it < 2; it++) {
            int id = tid + it * 256;
            int r = id >> 2, c4 = (id & 3) * 16;
            uint32_t sw = SWZ64(r * 64 + c4);
            cpa16(abase + sw, (const char*)(ga + (size_t)r * DM) + c4);
            cpa16(bbase + sw, (const char*)(gb + (size_t)r * DM) + c4);
        }
        CPA_COMMIT();
    };

    float acc[2][8][4];
#pragma unroll
    for (int mi = 0; mi < 2; mi++)
#pragma unroll
        for (int ni = 0; ni < 8; ni++)
#pragma unroll
            for (int q = 0; q < 4; q++) acc[mi][ni][q] = 0.f;

    load(0, 0); load(1, 1); load(2, 2);

    const int aRow = (lane & 15);
    const int aK   = (lane >> 4) << 3;
    const int bRow = (lane & 7) + ((lane >> 4) << 3);
    const int bK   = ((lane >> 3) & 1) << 3;

    for (int i = 0; i < NIT16; i++) {
        asm volatile("cp.async.wait_group 2;" ::: "memory");
        __syncthreads();
        if (i + 3 < NIT16) load(i + 3, (i + 3) & 3);
        else CPA_COMMIT();

        uint32_t abase = sb + (i & 3) * 16384;
        uint32_t bbase = abase + 8192;
#pragma unroll
        for (int kk = 0; kk < BK; kk += 16) {
            uint32_t a[2][4];
#pragma unroll
            for (int mi = 0; mi < 2; mi++) {
                int row = wm * 32 + mi * 16 + aRow;
                ldsm4(a[mi][0], a[mi][1], a[mi][2], a[mi][3],
                      abase + SWZ64(row * 64 + (kk + aK) * 2));
            }
            uint32_t b[4][4];
#pragma unroll
            for (int ng = 0; ng < 4; ng++) {
                int row = wn * 64 + ng * 16 + bRow;
                ldsm4(b[ng][0], b[ng][1], b[ng][2], b[ng][3],
                      bbase + SWZ64(row * 64 + (kk + bK) * 2));
            }
#pragma unroll
            for (int mi = 0; mi < 2; mi++)
#pragma unroll
                for (int ni = 0; ni < 8; ni++) {
                    int ng = ni >> 1, half = ni & 1;
                    mma16816h(acc[mi][ni], a[mi][0], a[mi][1], a[mi][2], a[mi][3],
                              b[ng][half * 2], b[ng][half * 2 + 1]);
                }
        }
    }

    const int g = lane >> 2, tig = lane & 3;
#pragma unroll
    for (int mi = 0; mi < 2; mi++) {
        int r0 = rowBase + wm * 32 + mi * 16 + g;
        int r1 = r0 + 8;
#pragma unroll
        for (int ni = 0; ni < 8; ni++) {
            int c = colBase + wn * 64 + ni * 8 + tig * 2;
            float bx = __ldg(&bias[c]), by = __ldg(&bias[c + 1]);
            if (HALF_OUT) {
                __half* C = (__half*)Cv;
                *reinterpret_cast<uint32_t*>(C + (size_t)r0 * DM + c) =
                    pack_h2(acc[mi][ni][0] + bx, acc[mi][ni][1] + by);
                *reinterpret_cast<uint32_t*>(C + (size_t)r1 * DM + c) =
                    pack_h2(acc[mi][ni][2] + bx, acc[mi][ni][3] + by);
            } else {
                float* C = (float*)Cv;
                float2 v0 = make_float2(acc[mi][ni][0] + bx, acc[mi][ni][1] + by);
                float2 v1 = make_float2(acc[mi][ni][2] + bx, acc[mi][ni][3] + by);
                *reinterpret_cast<float2*>(C + (size_t)r0 * DM + c) = v0;
                *reinterpret_cast<float2*>(C + (size_t)r1 * DM + c) = v1;
            }
        }
    }
}

// fused value (fp16) + query (split-bf16 full + narrow) GEMM
__global__ __launch_bounds__(256, 2)
void gemm_vq(const float* __restrict__ biasV, float* __restrict__ CQ) {
    extern __shared__ char smem[];                  // 4 * 16384
    uint32_t sb = smem_u32(smem);
    int t = blockIdx.x;
    if (t < VTILES) {
        int rowBase = (t >> 1) * 128, colBase = (t & 1) * 128;
        gemm_body16<true>(g_AVh, g_WTVh, biasV, g_v, rowBase, colBase, sb);
    } else if (t < VTILES + QFULL) {
        t -= VTILES;
        int rowBase = (t >> 1) * 128, colBase = (t & 1) * 128;
        gemm_bodyQ(g_Abig, g_WTQ, g_bcat, CQ, PCOLS, rowBase, colBase, sb);
    } else {
        t -= VTILES + QFULL;
        gemm_bodyQN(g_Abig, g_WTQ, g_bcat, CQ, t * 128, sb);
    }
}

// output GEMM (fp16 inputs, fp32 out)
__global__ __launch_bounds__(256, 2)
void gemm_out(const float* __restrict__ bias, float* __restrict__ C) {
    extern __shared__ char smem[];
    uint32_t sb = smem_u32(smem);
    int rowBase = (blockIdx.x >> 1) * 128, colBase = (blockIdx.x & 1) * 128;
    gemm_body16<false>(g_mid, g_WTOh, bias, C, rowBase, colBase, sb);
}

// ---------------- deformable sampling: 4 (q,h) per warp (round-15 proven) ----------------
__device__ __forceinline__ float tanh_approx(float x) {
    float r;
    asm("tanh.approx.f32 %0, %1;" : "=f"(r) : "f"(x));
    return r;
}

__global__ __launch_bounds__(256)
void sample_kernel(const float* __restrict__ refp) {
    __shared__ float2 s_tap[8][4][64];    // [warp][gid-in-warp][tap] = (w, idx bits)

    const int warp = threadIdx.x >> 5;
    const int lane = threadIdx.x & 31;
    const int gbase = (blockIdx.x * 8 + warp) * 4;  // h-major: gid = h*32768 + bq

    // ---- tap prep: two passes, 32 lanes each covering 2 gids ----
#pragma unroll
    for (int jj = 0; jj < 2; jj++) {
        const int sub = (lane >> 4) + jj * 2;       // 0..3
        const int li  = lane & 15;                  // sample 0..15
        const int gid = gbase + sub;
        const int h  = gid >> 15;
        const int bq = gid & 32767;

        const float* __restrict__ P = g_P + (size_t)bq * PCOLS;
        const int hL = h * LL;

        const int l  = li >> 2, k = li & 3;
        const int kt = k >> 1,  kf = k & 1;
        const float t = tanh_approx(P[(hL + l) * 2 + kt]);
        const float f = tanh_approx(P[64 + (hL + l) * 2 + kf]);

        float e0 = P[128 + hL + 0], e1 = P[128 + hL + 1];
        float e2 = P[128 + hL + 2], e3 = P[128 + hL + 3];
        float mx = fmaxf(fmaxf(e0, e1), fmaxf(e2, e3));
        float x0e = __expf(e0 - mx), x1e = __expf(e1 - mx);
        float x2e = __expf(e2 - mx), x3e = __expf(e3 - mx);
        float lsum = x0e + x1e + x2e + x3e;
        float lwv = (l == 0 ? x0e : l == 1 ? x1e : l == 2 ? x2e : x3e);

        const float* pp = P + 160 + (hL + l) * 4;
        float p0 = pp[0], p1 = pp[1], p2 = pp[2], p3 = pp[3];
        float pm = fmaxf(fmaxf(p0, p1), fmaxf(p2, p3));
        float q0 = __expf(p0 - pm), q1 = __expf(p1 - pm);
        float q2 = __expf(p2 - pm), q3 = __expf(p3 - pm);
        float psum = q0 + q1 + q2 + q3;
        float pwv = (k == 0 ? q0 : k == 1 ? q1 : k == 2 ? q2 : q3);

        const float a = __fdividef(lwv * pwv, lsum * psum);

        const float* rp = refp + (size_t)bq * (LL * 2);
        const int   Wl = c_Wl[l];
        const int   start = c_lsi[l];
        const float fWl = (float)Wl;
        float lx = rp[l * 2 + 0] + t * c_inv[l];
        float ly = rp[l * 2 + 1] + f * c_inv[l];
        lx = fminf(fmaxf(lx, 0.f), 1.f);
        ly = fminf(fmaxf(ly, 0.f), 1.f);
        float x = lx * fWl - 0.5f;
        float y = ly * fWl - 0.5f;       // Hl == Wl for all levels
        float x0f = floorf(x), y0f = floorf(y);
        float wx1 = x - x0f, wy1 = y - y0f;
        float wx0 = 1.f - wx1, wy0 = 1.f - wy1;
        int x0 = (int)x0f, y0 = (int)y0f;

#pragma unroll
        for (int j = 0; j < 4; j++) {
            int xi = x0 + (j & 1), yi = y0 + (j >> 1);
            float w = a * ((j & 1) ? wx1 : wx0) * ((j >> 1) ? wy1 : wy0);
            bool valid = (xi >= 0) & (xi < Wl) & (yi >= 0) & (yi < Wl);
            int xc = min(max(xi, 0), Wl - 1);
            int yc = min(max(yi, 0), Wl - 1);
            s_tap[warp][sub][li * 4 + j] =
                make_float2(valid ? w : 0.f, __int_as_float(start + yc * Wl + xc));
        }
    }
    __syncwarp();

    // ---- gather: 8 lanes per gid, 4 channels per lane ----
    const int sub = lane >> 3;                      // 0..3
    const int ch  = (lane & 7) * 4;                 // channel base 0..28
    const int gid = gbase + sub;
    const int h  = gid >> 15;
    const int bq = gid & 32767;
    const int b  = bq >> 13;                        // NQ=8192

    const uint2* __restrict__ vb = reinterpret_cast<const uint2*>(
        g_v + (size_t)b * NVV * DM + h * DHD + ch);
    float acc0 = 0.f, acc1 = 0.f, acc2 = 0.f, acc3 = 0.f;
#pragma unroll 16
    for (int t = 0; t < 64; t++) {
        float2 tp = s_tap[warp][sub][t];
        uint2 raw = vb[(size_t)__float_as_int(tp.y) * (DM / 4)];
        float2 v01 = __half22float2(*reinterpret_cast<__half2*>(&raw.x));
        float2 v23 = __half22float2(*reinterpret_cast<__half2*>(&raw.y));
        acc0 += tp.x * v01.x;
        acc1 += tp.x * v01.y;
        acc2 += tp.x * v23.x;
        acc3 += tp.x * v23.y;
    }

    // write fp16 quad into g_mid for the output GEMM
    const int col = h * DHD + ch;
    *reinterpret_cast<uint2*>(g_mid + (size_t)bq * DM + col) =
        make_uint2(pack_h2(acc0, acc1), pack_h2(acc2, acc3));
}

// ---------------- launch ----------------
extern "C" void kernel_launch(void* const* d_in, const int* in_sizes, int n_in,
                              void* d_out, int out_size) {
    const float* query  = (const float*)d_in[0];
    const float* refp   = (const float*)d_in[1];
    const float* value  = (const float*)d_in[2];
    const float* W_time = (const float*)d_in[5];
    const float* b_time = (const float*)d_in[6];
    const float* W_freq = (const float*)d_in[7];
    const float* b_freq = (const float*)d_in[8];
    const float* W_lvl  = (const float*)d_in[9];
    const float* b_lvl  = (const float*)d_in[10];
    const float* W_pt   = (const float*)d_in[11];
    const float* b_pt   = (const float*)d_in[12];
    const float* W_v    = (const float*)d_in[13];
    const float* b_v    = (const float*)d_in[14];
    const float* W_o    = (const float*)d_in[15];
    const float* b_o    = (const float*)d_in[16];
    float* out = (float*)d_out;

    float* p_P;
    cudaGetSymbolAddress((void**)&p_P, g_P);

    const int GEMM_SMEM = 4 * 16384;   // 64 KB
    cudaFuncSetAttribute(gemm_vq,  cudaFuncAttributeMaxDynamicSharedMemorySize, GEMM_SMEM);
    cudaFuncSetAttribute(gemm_out, cudaFuncAttributeMaxDynamicSharedMemorySize, GEMM_SMEM);

    // 1) all conversions in ONE vectorized launch
    conv_all<<<CB_WQ, 256>>>(query, value, W_v, W_o,
                             W_time, b_time, W_freq, b_freq,
                             W_lvl, b_lvl, W_pt, b_pt);

    // 2) fused value(fp16) + query(split-bf16, full+narrow) GEMMs
    gemm_vq<<<VTILES + QFULL + QNARROW, 256, GEMM_SMEM>>>(b_v, p_P);

    // 3) deformable sampling (4 gids/warp, 8B gathers) -> fp16 g_mid
    sample_kernel<<<(BB * NQ * HH) / 32, 256>>>(refp);

    // 4) output GEMM (fp16): out = mid @ W_o + b_o   [32768 x 256]
    gemm_out<<<512, 256, GEMM_SMEM>>>(b_o, out);
}